// round 15
// baseline (speedup 1.0000x reference)
#include <cuda_runtime.h>

#define B      128
#define IN     256
#define HS     512
#define OUT    256
#define RG     8      // rows per CTA (one warp per row)
#define SG     8      // samples per CTA
#define GROUPN 512u   // arrivals per sample = 64 CTAs x 8 warps

__device__ float        g_acc_da[B];   // zeroed at load; left zero by kernel
__device__ unsigned int g_cnt[B];
__device__ unsigned int g_done[B];

// Pipelined phase-3 for sample j (compile-time j via full unroll):
// warp-level spin on the per-sample counter, then clipped hebb update of this
// warp's row. hebb re-read hits L1/L2 (loaded one sample-step earlier).
#define FINISH_SAMPLE(j)                                                          \
do {                                                                              \
    const int bj = bbase + (j);                                                   \
    float da;                                                                     \
    if (lane == 0) {                                                              \
        unsigned c;                                                              \
        do {                                                                      \
            asm volatile("ld.acquire.gpu.u32 %0, [%1];" : "=r"(c) : "l"(g_cnt + bj)); \
            if (c < GROUPN) __nanosleep(32);                                      \
        } while (c < GROUPN);                                                     \
        da = tanhf(__ldcg(&g_acc_da[bj]) + dab);                                  \
        __threadfence();  /* order acc read before done signal (R11 bug class) */ \
        const unsigned old = atomicAdd(&g_done[bj], 1u);                          \
        if (old == GROUPN - 1) {   /* last consumer: reset for graph replay */    \
            g_acc_da[bj] = 0.f;                                                   \
            g_cnt[bj]    = 0u;                                                    \
            __threadfence();                                                      \
            g_done[bj]   = 0u;                                                    \
        }                                                                         \
    }                                                                             \
    da = __shfl_sync(0xffffffffu, da, 0);                                         \
    const float coef = da * hsv[j];                                               \
    const size_t roff = ((size_t)bj * HS + i) * (HS / 4);                         \
    const float4* hbp = (const float4*)hebb + roff;                               \
    float4*       obp = (float4*)hebb_new + roff;                                 \
    const float4* qp  = (const float4*)(hidden + (size_t)bj * HS);                \
    _Pragma("unroll")                                                             \
    for (int k = 0; k < 4; ++k) {                                                 \
        const float4 hv = __ldcs(hbp + lane + 32 * k);                            \
        const float4 xv = __ldg(qp + lane + 32 * k);                              \
        float4 r;                                                                 \
        r.x = fminf(1.f, fmaxf(-1.f, fmaf(coef, xv.x, hv.x)));                    \
        r.y = fminf(1.f, fmaxf(-1.f, fmaf(coef, xv.y, hv.y)));                    \
        r.z = fminf(1.f, fmaxf(-1.f, fmaf(coef, xv.z, hv.z)));                    \
        r.w = fminf(1.f, fmaxf(-1.f, fmaf(coef, xv.w, hv.w)));                    \
        __stcs(obp + lane + 32 * k, r);                                           \
    }                                                                             \
} while (0)

__global__ __launch_bounds__(256, 3) void k_fused(
    const float* __restrict__ inputs, const float* __restrict__ hidden,
    const float* __restrict__ hebb,   const float* __restrict__ i2h_w,
    const float* __restrict__ i2h_b,  const float* __restrict__ w,
    const float* __restrict__ alpha,  const float* __restrict__ h2da_w,
    const float* __restrict__ h2da_b, const float* __restrict__ h2o_w,
    const float* __restrict__ h2o_b,  const float* __restrict__ h2v_w,
    const float* __restrict__ h2v_b,  float* __restrict__ hactiv,
    float* __restrict__ hebb_new,     float* __restrict__ activout,
    float* __restrict__ valueout)
{
    const int tid   = threadIdx.x;
    const int warp  = tid >> 5;
    const int lane  = tid & 31;
    const int i     = blockIdx.x * RG + warp;
    const int bbase = blockIdx.y * SG;

    __shared__ float4 shW[RG * HS / 4];    // 16 KB: this CTA's 8 w-rows
    __shared__ float4 shA[RG * HS / 4];    // 16 KB: this CTA's 8 alpha-rows
    __shared__ float4 shX[SG * IN / 4];    //  8 KB: 8 samples' inputs

    {
        const float4* gw = (const float4*)(w     + (size_t)blockIdx.x * RG * HS);
        const float4* ga = (const float4*)(alpha + (size_t)blockIdx.x * RG * HS);
        for (int t = tid; t < RG * HS / 4; t += 256) { shW[t] = gw[t]; shA[t] = ga[t]; }
        const float4* gx = (const float4*)(inputs + (size_t)bbase * IN);
        for (int t = tid; t < SG * IN / 4; t += 256) shX[t] = gx[t];
    }

    float4 iw[2];
    {
        const float4* x4 = (const float4*)(i2h_w + (size_t)i * IN);
#pragma unroll
        for (int k = 0; k < 2; ++k) iw[k] = x4[lane + 32 * k];
    }
    const float bias = i2h_b[i];
    const float wda  = __ldg(h2da_w + i);
    const float dab  = __ldg(h2da_b);

    __syncthreads();

    float hsv[SG];   // own-row hactiv per sample (static indices via full unroll)

    // ---- pipelined main loop: phase1(bb) then phase3(bb-1) ----
#pragma unroll
    for (int bb = 0; bb < SG; ++bb) {
        const int b = bbase + bb;
        const float4* hr = (const float4*)(hebb + ((size_t)b * HS + i) * HS);
        const float4* q  = (const float4*)(hidden + (size_t)b * HS);

        float4 hbv[4];
#pragma unroll
        for (int k = 0; k < 4; ++k) hbv[k] = hr[lane + 32 * k];   // plain: cache for phase 3

        float sa = 0.f, sb = 0.f;
#pragma unroll
        for (int k = 0; k < 4; ++k) {
            const float4 wv = shW[warp * (HS / 4) + lane + 32 * k];
            const float4 av = shA[warp * (HS / 4) + lane + 32 * k];
            const float4 d  = __ldg(q + lane + 32 * k);
            sa = fmaf(fmaf(av.x, hbv[k].x, wv.x), d.x, sa);
            sb = fmaf(fmaf(av.y, hbv[k].y, wv.y), d.y, sb);
            sa = fmaf(fmaf(av.z, hbv[k].z, wv.z), d.z, sa);
            sb = fmaf(fmaf(av.w, hbv[k].w, wv.w), d.w, sb);
        }
#pragma unroll
        for (int k = 0; k < 2; ++k) {
            const float4 xv = shX[bb * (IN / 4) + lane + 32 * k];
            sa = fmaf(iw[k].x, xv.x, sa); sb = fmaf(iw[k].y, xv.y, sb);
            sa = fmaf(iw[k].z, xv.z, sa); sb = fmaf(iw[k].w, xv.w, sb);
        }
        float s = sa + sb;
#pragma unroll
        for (int off = 16; off; off >>= 1) s += __shfl_xor_sync(0xffffffffu, s, off);

        float h;
        if (lane == 0) {
            h = tanhf(s + bias);
            hactiv[(size_t)b * HS + i] = h;
            atomicAdd(&g_acc_da[b], wda * h);   // per-warp partial, posted NOW
            __threadfence();
            atomicAdd(&g_cnt[b], 1u);
        }
        h = __shfl_sync(0xffffffffu, h, 0);
        hsv[bb] = h;

        if (bb >= 1) FINISH_SAMPLE(bb - 1);     // overlap update with next phase1
    }
    FINISH_SAMPLE(SG - 1);

    // ---- fused heads (hactiv of this group complete & L2-hot) ----
    const int x = blockIdx.x;
    if (x < OUT / RG) {                         // x in [0,32): activout
        const int o = x * RG + warp;
        const float4* wrow = (const float4*)(h2o_w + (size_t)o * HS);
        float4 wv[4];
#pragma unroll
        for (int k = 0; k < 4; ++k) wv[k] = wrow[lane + 32 * k];
        const float obias = h2o_b[o];
#pragma unroll 2
        for (int bb = 0; bb < SG; ++bb) {
            const float4* ha = (const float4*)(hactiv + (size_t)(bbase + bb) * HS);
            float s = 0.f;
#pragma unroll
            for (int k = 0; k < 4; ++k) {
                const float4 hv = ha[lane + 32 * k];
                s = fmaf(wv[k].x, hv.x, s); s = fmaf(wv[k].y, hv.y, s);
                s = fmaf(wv[k].z, hv.z, s); s = fmaf(wv[k].w, hv.w, s);
            }
#pragma unroll
            for (int off = 16; off; off >>= 1) s += __shfl_xor_sync(0xffffffffu, s, off);
            if (lane == 0) activout[(size_t)(bbase + bb) * OUT + o] = s + obias;
        }
    } else if (x == OUT / RG) {                 // x == 32: valueout
        const int b = bbase + warp;
        const float4* vw = (const float4*)h2v_w;
        const float4* ha = (const float4*)(hactiv + (size_t)b * HS);
        float s = 0.f;
#pragma unroll
        for (int k = 0; k < 4; ++k) {
            const float4 v = vw[lane + 32 * k];
            const float4 hv = ha[lane + 32 * k];
            s = fmaf(v.x, hv.x, s); s = fmaf(v.y, hv.y, s);
            s = fmaf(v.z, hv.z, s); s = fmaf(v.w, hv.w, s);
        }
#pragma unroll
        for (int off = 16; off; off >>= 1) s += __shfl_xor_sync(0xffffffffu, s, off);
        if (lane == 0) valueout[b] = s + h2v_b[0];
    }
}

// ---------------------------------------------------------------------------
extern "C" void kernel_launch(void* const* d_in, const int* in_sizes, int n_in,
                              void* d_out, int out_size)
{
    const float* inputs = (const float*)d_in[0];
    const float* hidden = (const float*)d_in[1];
    const float* hebb   = (const float*)d_in[2];
    const float* i2h_w  = (const float*)d_in[3];
    const float* i2h_b  = (const float*)d_in[4];
    const float* w      = (const float*)d_in[5];
    const float* alpha  = (const float*)d_in[6];
    const float* h2o_w  = (const float*)d_in[7];
    const float* h2o_b  = (const float*)d_in[8];
    const float* h2v_w  = (const float*)d_in[9];
    const float* h2v_b  = (const float*)d_in[10];
    const float* h2da_w = (const float*)d_in[11];
    const float* h2da_b = (const float*)d_in[12];

    float* out      = (float*)d_out;
    float* activout = out;                                // [B, OUT]
    float* valueout = activout + (size_t)B * OUT;         // [B, 1]
    float* hactiv   = valueout + B;                       // [B, HS]
    float* hebb_new = hactiv + (size_t)B * HS;            // [B, HS, HS]

    k_fused<<<dim3(HS / RG, B / SG), 256>>>(
        inputs, hidden, hebb, i2h_w, i2h_b, w, alpha,
        h2da_w, h2da_b, h2o_w, h2o_b, h2v_w, h2v_b,
        hactiv, hebb_new, activout, valueout);
}

// round 16
// speedup vs baseline: 3.7895x; 3.7895x over previous
#include <cuda_runtime.h>

#define B      128
#define IN     256
#define HS     512
#define OUT    256
#define RG     8      // rows per CTA (one warp per row)
#define SG     8      // samples per CTA
#define NCTA_PER_SAMPLE (HS / RG)   // 64 arrivals per sample

__device__ float        g_acc_da[B];   // zeroed at load; left zero by kernel
__device__ unsigned int g_cnt[B];
__device__ unsigned int g_done[B];

// ---------------------------------------------------------------------------
// Two-pass fused kernel (R8 skeleton), register-dieted for 4 CTAs/SM:
//  all per-row weights (w, alpha, i2h_w) live in SMEM; sample loop not
//  unrolled so only ~16 hebb regs are live; single bulk spin per CTA.
// ---------------------------------------------------------------------------
__global__ __launch_bounds__(256, 4) void k_fused(
    const float* __restrict__ inputs, const float* __restrict__ hidden,
    const float* __restrict__ hebb,   const float* __restrict__ i2h_w,
    const float* __restrict__ i2h_b,  const float* __restrict__ w,
    const float* __restrict__ alpha,  const float* __restrict__ h2da_w,
    const float* __restrict__ h2da_b, const float* __restrict__ h2o_w,
    const float* __restrict__ h2o_b,  const float* __restrict__ h2v_w,
    const float* __restrict__ h2v_b,  float* __restrict__ hactiv,
    float* __restrict__ hebb_new,     float* __restrict__ activout,
    float* __restrict__ valueout)
{
    const int tid   = threadIdx.x;
    const int warp  = tid >> 5;
    const int lane  = tid & 31;
    const int i     = blockIdx.x * RG + warp;
    const int bbase = blockIdx.y * SG;

    __shared__ float4 shW[RG * HS / 4];    // 16 KB: this CTA's 8 w-rows
    __shared__ float4 shA[RG * HS / 4];    // 16 KB: this CTA's 8 alpha-rows
    __shared__ float4 shI[RG * IN / 4];    //  8 KB: this CTA's 8 i2h_w rows
    __shared__ float4 shX[SG * IN / 4];    //  8 KB: 8 samples' inputs
    __shared__ float  sh_hact[SG * RG];
    __shared__ float  sh_wda[RG];
    __shared__ float  sh_da[SG];

    // preload weights + inputs
    {
        const float4* gw = (const float4*)(w     + (size_t)blockIdx.x * RG * HS);
        const float4* ga = (const float4*)(alpha + (size_t)blockIdx.x * RG * HS);
        for (int t = tid; t < RG * HS / 4; t += 256) { shW[t] = gw[t]; shA[t] = ga[t]; }
        const float4* gi = (const float4*)(i2h_w + (size_t)blockIdx.x * RG * IN);
        for (int t = tid; t < RG * IN / 4; t += 256) shI[t] = gi[t];
        const float4* gx = (const float4*)(inputs + (size_t)bbase * IN);
        for (int t = tid; t < SG * IN / 4; t += 256) shX[t] = gx[t];
        if (tid < RG) sh_wda[tid] = h2da_w[blockIdx.x * RG + tid];
    }
    const float bias = i2h_b[i];

    __syncthreads();

    // ---------------- phase 1: hactiv, one sample per iteration -----------
#pragma unroll 1
    for (int bb = 0; bb < SG; ++bb) {
        const int b = bbase + bb;
        const float4* hr = (const float4*)(hebb + ((size_t)b * HS + i) * HS);
        const float4* q  = (const float4*)(hidden + (size_t)b * HS);

        float4 hb[4];
#pragma unroll
        for (int k = 0; k < 4; ++k) hb[k] = hr[lane + 32 * k];

        float sa = 0.f, sb = 0.f;
#pragma unroll
        for (int k = 0; k < 4; ++k) {
            const float4 wv = shW[warp * (HS / 4) + lane + 32 * k];
            const float4 av = shA[warp * (HS / 4) + lane + 32 * k];
            const float4 d  = __ldg(q + lane + 32 * k);
            sa = fmaf(fmaf(av.x, hb[k].x, wv.x), d.x, sa);
            sb = fmaf(fmaf(av.y, hb[k].y, wv.y), d.y, sb);
            sa = fmaf(fmaf(av.z, hb[k].z, wv.z), d.z, sa);
            sb = fmaf(fmaf(av.w, hb[k].w, wv.w), d.w, sb);
        }
#pragma unroll
        for (int k = 0; k < 2; ++k) {
            const float4 xv = shX[bb * (IN / 4) + lane + 32 * k];
            const float4 vv = shI[warp * (IN / 4) + lane + 32 * k];
            sa = fmaf(vv.x, xv.x, sa); sb = fmaf(vv.y, xv.y, sb);
            sa = fmaf(vv.z, xv.z, sa); sb = fmaf(vv.w, xv.w, sb);
        }
        float s = sa + sb;
#pragma unroll
        for (int off = 16; off; off >>= 1) s += __shfl_xor_sync(0xffffffffu, s, off);
        if (lane == 0) {
            const float v = tanhf(s + bias);
            hactiv[(size_t)b * HS + i] = v;
            sh_hact[bb * RG + warp] = v;
        }
    }
    __syncthreads();

    // ---------------- da partials + counter (release) ----------------
    if (tid < SG) {
        const int b = bbase + tid;
        float sum = 0.f;
#pragma unroll
        for (int wv = 0; wv < RG; ++wv) sum += sh_wda[wv] * sh_hact[tid * RG + wv];
        atomicAdd(&g_acc_da[b], sum);
        __threadfence();
        atomicAdd(&g_cnt[b], 1u);
    }

    // ---------------- single bulk spin (acquire), consume, self-reset -----
    if (tid < SG) {
        const int b = bbase + tid;
        unsigned c;
        do {
            asm volatile("ld.acquire.gpu.u32 %0, [%1];" : "=r"(c) : "l"(g_cnt + b));
            if (c < NCTA_PER_SAMPLE) __nanosleep(64);
        } while (c < NCTA_PER_SAMPLE);
        sh_da[tid] = tanhf(__ldcg(&g_acc_da[b]) + h2da_b[0]);
        __threadfence();   // order acc read before done signal (R11 bug class)
        const unsigned old = atomicAdd(&g_done[b], 1u);
        if (old == NCTA_PER_SAMPLE - 1) {   // last consumer: reset for replay
            g_acc_da[b] = 0.f;
            g_cnt[b]    = 0u;
            __threadfence();
            g_done[b]   = 0u;
        }
    }
    __syncthreads();

    // ---------------- phase 3: hebb update (L2-hot re-read, reversed) -----
#pragma unroll 1
    for (int bb = SG - 1; bb >= 0; --bb) {
        const float coef = sh_da[bb] * sh_hact[bb * RG + warp];
        const size_t roff = ((size_t)(bbase + bb) * HS + i) * HS;
        const float4* hb = (const float4*)(hebb + roff);
        float4*       ob = (float4*)(hebb_new + roff);
        const float4* q  = (const float4*)(hidden + (size_t)(bbase + bb) * HS);
#pragma unroll
        for (int k = 0; k < 4; ++k) {
            const float4 h = __ldcs(hb + lane + 32 * k);
            const float4 x = __ldg(q + lane + 32 * k);
            float4 r;
            r.x = fminf(1.f, fmaxf(-1.f, fmaf(coef, x.x, h.x)));
            r.y = fminf(1.f, fmaxf(-1.f, fmaf(coef, x.y, h.y)));
            r.z = fminf(1.f, fmaxf(-1.f, fmaf(coef, x.z, h.z)));
            r.w = fminf(1.f, fmaxf(-1.f, fmaf(coef, x.w, h.w)));
            __stcs(ob + lane + 32 * k, r);
        }
    }

    // ---------------- fused heads (hactiv is L2-hot) ----------------------
    const int x = blockIdx.x;
    if (x < OUT / RG) {                         // x in [0,32): activout
        const int o = x * RG + warp;
        const float4* wrow = (const float4*)(h2o_w + (size_t)o * HS);
        const float obias = h2o_b[o];
#pragma unroll 1
        for (int bb = 0; bb < SG; ++bb) {
            const float4* ha = (const float4*)(hactiv + (size_t)(bbase + bb) * HS);
            float s = 0.f;
#pragma unroll
            for (int k = 0; k < 4; ++k) {
                const float4 h = ha[lane + 32 * k];
                const float4 wv = __ldg(wrow + lane + 32 * k);
                s = fmaf(wv.x, h.x, s); s = fmaf(wv.y, h.y, s);
                s = fmaf(wv.z, h.z, s); s = fmaf(wv.w, h.w, s);
            }
#pragma unroll
            for (int off = 16; off; off >>= 1) s += __shfl_xor_sync(0xffffffffu, s, off);
            if (lane == 0) activout[(size_t)(bbase + bb) * OUT + o] = s + obias;
        }
    } else if (x == OUT / RG) {                 // x == 32: valueout
        const int b = bbase + warp;
        const float4* vw = (const float4*)h2v_w;
        const float4* ha = (const float4*)(hactiv + (size_t)b * HS);
        float s = 0.f;
#pragma unroll
        for (int k = 0; k < 4; ++k) {
            const float4 v = vw[lane + 32 * k];
            const float4 h = ha[lane + 32 * k];
            s = fmaf(v.x, h.x, s); s = fmaf(v.y, h.y, s);
            s = fmaf(v.z, h.z, s); s = fmaf(v.w, h.w, s);
        }
#pragma unroll
        for (int off = 16; off; off >>= 1) s += __shfl_xor_sync(0xffffffffu, s, off);
        if (lane == 0) valueout[b] = s + h2v_b[0];
    }
}

// ---------------------------------------------------------------------------
extern "C" void kernel_launch(void* const* d_in, const int* in_sizes, int n_in,
                              void* d_out, int out_size)
{
    const float* inputs = (const float*)d_in[0];
    const float* hidden = (const float*)d_in[1];
    const float* hebb   = (const float*)d_in[2];
    const float* i2h_w  = (const float*)d_in[3];
    const float* i2h_b  = (const float*)d_in[4];
    const float* w      = (const float*)d_in[5];
    const float* alpha  = (const float*)d_in[6];
    const float* h2o_w  = (const float*)d_in[7];
    const float* h2o_b  = (const float*)d_in[8];
    const float* h2v_w  = (const float*)d_in[9];
    const float* h2v_b  = (const float*)d_in[10];
    const float* h2da_w = (const float*)d_in[11];
    const float* h2da_b = (const float*)d_in[12];

    float* out      = (float*)d_out;
    float* activout = out;                                // [B, OUT]
    float* valueout = activout + (size_t)B * OUT;         // [B, 1]
    float* hactiv   = valueout + B;                       // [B, HS]
    float* hebb_new = hactiv + (size_t)B * HS;            // [B, HS, HS]

    k_fused<<<dim3(HS / RG, B / SG), 256>>>(
        inputs, hidden, hebb, i2h_w, i2h_b, w, alpha,
        h2da_w, h2da_b, h2o_w, h2o_b, h2v_w, h2v_b,
        hactiv, hebb_new, activout, valueout);
}